// round 4
// baseline (speedup 1.0000x reference)
#include <cuda_runtime.h>
#include <cuda_bf16.h>
#include <cstddef>

// Problem constants
#define B_SZ   2
#define T_SEQ  2048
#define D_MOD  1024
#define NH     16
#define DH     64
#define M_TOT  (B_SZ * T_SEQ)   // 4096 rows
#define NCOL   (NH * DH)        // 1024 cols (== D_MOD)

// Scratch (allocation-free rule: __device__ globals)
__device__ float g_q[M_TOT * NCOL];
__device__ float g_k[M_TOT * NCOL];
__device__ float g_v[M_TOT * NCOL];
__device__ float g_attn[M_TOT * NCOL];

// ---------------------------------------------------------------------------
// SGEMM: C[M,N] = A[M,K] @ B[K,N] + bias[N]
// 128x128 block, BK=16, 8x8 per thread, 256 threads.
// ---------------------------------------------------------------------------
__global__ __launch_bounds__(256)
void sgemm_bias(const float* __restrict__ A, const float* __restrict__ B,
                const float* __restrict__ bias, float* __restrict__ C,
                int M, int N, int K) {
    constexpr int BM = 128, BN = 128, BK = 16, TM = 8, TN = 8;
    __shared__ float As[BK][BM];
    __shared__ float Bs[BK][BN];

    const int tid = threadIdx.x;
    const int tx = tid & 15;        // 0..15
    const int ty = tid >> 4;        // 0..15
    const int bm = blockIdx.y * BM;
    const int bn = blockIdx.x * BN;

    // A-tile loader mapping: 128 rows x 4 float4; 2 rows per thread
    const int arow  = tid >> 2;         // 0..63
    const int acol4 = (tid & 3) * 4;    // 0,4,8,12
    // B-tile loader mapping: 16 rows x 32 float4; 2 rows per thread
    const int brow  = tid >> 5;         // 0..7
    const int bcol4 = (tid & 31) * 4;   // 0..124

    float acc[TM][TN];
    #pragma unroll
    for (int i = 0; i < TM; ++i)
        #pragma unroll
        for (int j = 0; j < TN; ++j) acc[i][j] = 0.f;

    for (int k0 = 0; k0 < K; k0 += BK) {
        #pragma unroll
        for (int r = 0; r < 2; ++r) {
            int row = arow + r * 64;
            float4 va = *(const float4*)&A[(size_t)(bm + row) * K + k0 + acol4];
            As[acol4 + 0][row] = va.x;
            As[acol4 + 1][row] = va.y;
            As[acol4 + 2][row] = va.z;
            As[acol4 + 3][row] = va.w;
        }
        #pragma unroll
        for (int r = 0; r < 2; ++r) {
            int row = brow + r * 8;
            *(float4*)&Bs[row][bcol4] =
                *(const float4*)&B[(size_t)(k0 + row) * N + bn + bcol4];
        }
        __syncthreads();

        #pragma unroll
        for (int kk = 0; kk < BK; ++kk) {
            float af[TM], bf[TN];
            #pragma unroll
            for (int i = 0; i < TM; ++i) af[i] = As[kk][ty * TM + i];
            #pragma unroll
            for (int j = 0; j < TN; ++j) bf[j] = Bs[kk][tx * TN + j];
            #pragma unroll
            for (int i = 0; i < TM; ++i)
                #pragma unroll
                for (int j = 0; j < TN; ++j)
                    acc[i][j] += af[i] * bf[j];
        }
        __syncthreads();
    }

    #pragma unroll
    for (int i = 0; i < TM; ++i) {
        const int row = bm + ty * TM + i;
        #pragma unroll
        for (int j = 0; j < TN; j += 4) {
            const int col = bn + tx * TN + j;
            float4 v;
            v.x = acc[i][j + 0] + bias[col + 0];
            v.y = acc[i][j + 1] + bias[col + 1];
            v.z = acc[i][j + 2] + bias[col + 2];
            v.w = acc[i][j + 3] + bias[col + 3];
            *(float4*)&C[(size_t)row * N + col] = v;
        }
    }
}

// ---------------------------------------------------------------------------
// Causal flash attention, fp32. One CTA per (q-tile of 64, head, batch).
// q/k/v/o stored row-major [B*T, H*DH] (column block h*DH..h*DH+63 per head).
// ---------------------------------------------------------------------------
#define BQ 64
#define SPITCH 65  // padded row stride (conflict-free: 65 mod 32 = 1)

__global__ __launch_bounds__(256)
void flash_attn(const float* __restrict__ q, const float* __restrict__ k,
                const float* __restrict__ v, float* __restrict__ o) {
    const int qt = blockIdx.x;   // 0..31
    const int h  = blockIdx.y;   // 0..15
    const int b  = blockIdx.z;   // 0..1

    extern __shared__ float sm[];
    float* Qs   = sm;                    // 64*65
    float* Ks   = Qs + 64 * SPITCH;      // 64*65
    float* Vs   = Ks + 64 * SPITCH;      // 64*65
    float* S    = Vs + 64 * SPITCH;      // 64*65
    float* rowc = S + 64 * SPITCH;       // 64 (softmax correction)
    float* rowl = rowc + 64;             // 64 (final 1/l)

    const int tid = threadIdx.x;  // 256
    const int tx = tid & 15;
    const int ty = tid >> 4;
    const int tx4 = tx * 4;
    const int ty4 = ty * 4;
    const int q0 = qt * BQ;
    const float scale = 0.125f;   // 1/sqrt(64)

    // Load Q tile (64 rows x 64 cols): 4 float4 per thread
    #pragma unroll
    for (int it = 0; it < 4; ++it) {
        int row = (tid >> 4) + it * 16;
        int c4  = (tid & 15) * 4;
        float4 vq = *(const float4*)&q[(size_t)(b * T_SEQ + q0 + row) * NCOL + h * DH + c4];
        float* dst = &Qs[row * SPITCH + c4];
        dst[0] = vq.x; dst[1] = vq.y; dst[2] = vq.z; dst[3] = vq.w;
    }

    float m_reg = -1e30f, l_reg = 0.f;   // valid for tid < 64 (row tid)
    float oacc[4][4];
    #pragma unroll
    for (int i = 0; i < 4; ++i)
        #pragma unroll
        for (int j = 0; j < 4; ++j) oacc[i][j] = 0.f;

    for (int kt = 0; kt <= qt; ++kt) {
        const int k0 = kt * BQ;
        __syncthreads();   // previous iteration's readers of Ks/Vs/S done (+ Qs visible)

        // Load K and V tiles
        #pragma unroll
        for (int it = 0; it < 4; ++it) {
            int row = (tid >> 4) + it * 16;
            int c4  = (tid & 15) * 4;
            size_t base = (size_t)(b * T_SEQ + k0 + row) * NCOL + h * DH + c4;
            float4 vk = *(const float4*)&k[base];
            float4 vv = *(const float4*)&v[base];
            float* dk = &Ks[row * SPITCH + c4];
            dk[0] = vk.x; dk[1] = vk.y; dk[2] = vk.z; dk[3] = vk.w;
            float* dv = &Vs[row * SPITCH + c4];
            dv[0] = vv.x; dv[1] = vv.y; dv[2] = vv.z; dv[3] = vv.w;
        }
        __syncthreads();

        // S = scale * Q K^T (4x4 micro-tile per thread)
        float sacc[4][4];
        #pragma unroll
        for (int i = 0; i < 4; ++i)
            #pragma unroll
            for (int j = 0; j < 4; ++j) sacc[i][j] = 0.f;

        #pragma unroll 16
        for (int d = 0; d < DH; ++d) {
            float qf[4], kf[4];
            #pragma unroll
            for (int i = 0; i < 4; ++i) qf[i] = Qs[(ty4 + i) * SPITCH + d];
            #pragma unroll
            for (int j = 0; j < 4; ++j) kf[j] = Ks[(tx4 + j) * SPITCH + d];
            #pragma unroll
            for (int i = 0; i < 4; ++i)
                #pragma unroll
                for (int j = 0; j < 4; ++j)
                    sacc[i][j] += qf[i] * kf[j];
        }

        const bool diag = (kt == qt);
        #pragma unroll
        for (int i = 0; i < 4; ++i)
            #pragma unroll
            for (int j = 0; j < 4; ++j) {
                float s = sacc[i][j] * scale;
                if (diag && (k0 + tx4 + j) > (q0 + ty4 + i)) s = -1e30f;
                S[(ty4 + i) * SPITCH + tx4 + j] = s;
            }
        __syncthreads();

        // Online softmax per row (64 threads)
        if (tid < 64) {
            const float* srow = &S[tid * SPITCH];
            float m_new = m_reg;
            #pragma unroll 8
            for (int j = 0; j < BQ; ++j) m_new = fmaxf(m_new, srow[j]);
            float c = __expf(m_reg - m_new);
            float lsum = 0.f;
            float* prow = &S[tid * SPITCH];
            #pragma unroll 8
            for (int j = 0; j < BQ; ++j) {
                float p = __expf(srow[j] - m_new);
                prow[j] = p;
                lsum += p;
            }
            l_reg = l_reg * c + lsum;
            m_reg = m_new;
            rowc[tid] = c;
        }
        __syncthreads();

        // O = O * c + P @ V
        float ci[4];
        #pragma unroll
        for (int i = 0; i < 4; ++i) ci[i] = rowc[ty4 + i];
        #pragma unroll
        for (int i = 0; i < 4; ++i)
            #pragma unroll
            for (int j = 0; j < 4; ++j) oacc[i][j] *= ci[i];

        #pragma unroll 8
        for (int jj = 0; jj < BQ; ++jj) {
            float pv[4], vv[4];
            #pragma unroll
            for (int i = 0; i < 4; ++i) pv[i] = S[(ty4 + i) * SPITCH + jj];
            #pragma unroll
            for (int j = 0; j < 4; ++j) vv[j] = Vs[jj * SPITCH + tx4 + j];
            #pragma unroll
            for (int i = 0; i < 4; ++i)
                #pragma unroll
                for (int j = 0; j < 4; ++j)
                    oacc[i][j] += pv[i] * vv[j];
        }
    }

    // Finalize: divide by l and store
    if (tid < 64) rowl[tid] = 1.0f / l_reg;
    __syncthreads();

    float inv[4];
    #pragma unroll
    for (int i = 0; i < 4; ++i) inv[i] = rowl[ty4 + i];
    #pragma unroll
    for (int i = 0; i < 4; ++i) {
        size_t base = (size_t)(b * T_SEQ + q0 + ty4 + i) * NCOL + h * DH + tx4;
        float4 vo;
        vo.x = oacc[i][0] * inv[i];
        vo.y = oacc[i][1] * inv[i];
        vo.z = oacc[i][2] * inv[i];
        vo.w = oacc[i][3] * inv[i];
        *(float4*)&o[base] = vo;
    }
}

// ---------------------------------------------------------------------------
// Launch
// ---------------------------------------------------------------------------
extern "C" void kernel_launch(void* const* d_in, const int* in_sizes, int n_in,
                              void* d_out, int out_size) {
    const float* x  = (const float*)d_in[0];
    const float* wq = (const float*)d_in[1];
    const float* bq = (const float*)d_in[2];
    const float* wk = (const float*)d_in[3];
    const float* bk = (const float*)d_in[4];
    const float* wv = (const float*)d_in[5];
    const float* bv = (const float*)d_in[6];
    const float* wo = (const float*)d_in[7];
    const float* bo = (const float*)d_in[8];
    float* out = (float*)d_out;

    float *qp, *kp, *vp, *ap;
    cudaGetSymbolAddress((void**)&qp, g_q);
    cudaGetSymbolAddress((void**)&kp, g_k);
    cudaGetSymbolAddress((void**)&vp, g_v);
    cudaGetSymbolAddress((void**)&ap, g_attn);

    const int smem_bytes = (4 * 64 * SPITCH + 2 * 64) * (int)sizeof(float);
    cudaFuncSetAttribute(flash_attn, cudaFuncAttributeMaxDynamicSharedMemorySize,
                         smem_bytes);

    dim3 gg(NCOL / 128, M_TOT / 128);
    dim3 tt(256);

    sgemm_bias<<<gg, tt>>>(x, wq, bq, qp, M_TOT, NCOL, D_MOD);
    sgemm_bias<<<gg, tt>>>(x, wk, bk, kp, M_TOT, NCOL, D_MOD);
    sgemm_bias<<<gg, tt>>>(x, wv, bv, vp, M_TOT, NCOL, D_MOD);

    flash_attn<<<dim3(T_SEQ / BQ, NH, B_SZ), 256, smem_bytes>>>(qp, kp, vp, ap);

    sgemm_bias<<<gg, tt>>>(ap, wo, bo, out, M_TOT, NCOL, D_MOD);
}

// round 7
// speedup vs baseline: 1.4279x; 1.4279x over previous
#include <cuda_runtime.h>
#include <cuda_bf16.h>
#include <cstdint>
#include <cstddef>

// Problem constants
#define B_SZ   2
#define T_SEQ  2048
#define D_MOD  1024
#define NH     16
#define DH     64
#define M_TOT  (B_SZ * T_SEQ)   // 4096 rows
#define NCOL   (NH * DH)        // 1024 cols (== D_MOD)

// ---------------------------------------------------------------------------
// Scratch: one big __device__ buffer, carved on the host side.
//   q   : 0    (16 MB fp32)     k   : 16 MB      v   : 32 MB
//   attn: 48 MB                 xr  : 64 MB (tf32-rounded x, 16 MB)
//   wqT : 80 MB (4 MB each)     wkT : 84   wvT : 88   woT : 92
// total 96 MB
#define SCRATCH_BYTES (96u * 1024u * 1024u)
__device__ __align__(256) unsigned char g_scratch[SCRATCH_BYTES];

// ---------------------------------------------------------------------------
// tf32 round-to-nearest (rna) on an fp32 value; result stays in fp32 bits
// with the low 13 mantissa bits zero, so HMMA's truncation is a no-op.
// ---------------------------------------------------------------------------
__device__ __forceinline__ float tf32_rna(float v) {
    uint32_t u;
    asm("cvt.rna.tf32.f32 %0, %1;" : "=r"(u) : "f"(v));
    return __uint_as_float(u);
}

// ---------------------------------------------------------------------------
// Elementwise tf32 rounding (x -> xr), vectorized x4
// ---------------------------------------------------------------------------
__global__ __launch_bounds__(256)
void round_tf32_4(const float* __restrict__ in, float* __restrict__ out, int n4) {
    int i = blockIdx.x * blockDim.x + threadIdx.x;
    if (i >= n4) return;
    float4 v = ((const float4*)in)[i];
    v.x = tf32_rna(v.x);
    v.y = tf32_rna(v.y);
    v.z = tf32_rna(v.z);
    v.w = tf32_rna(v.w);
    ((float4*)out)[i] = v;
}

// ---------------------------------------------------------------------------
// Weight transpose + tf32 round: w[K=1024][N=1024] -> wT[N][K]
// ---------------------------------------------------------------------------
__global__ __launch_bounds__(256)
void cvt_T(const float* __restrict__ w, float* __restrict__ wt) {
    __shared__ float t[32][33];
    const int n0 = blockIdx.x * 32;
    const int k0 = blockIdx.y * 32;
    const int tx = threadIdx.x;       // 0..31
    const int ty = threadIdx.y;       // 0..7
    #pragma unroll
    for (int i = 0; i < 32; i += 8)
        t[ty + i][tx] = w[(size_t)(k0 + ty + i) * NCOL + n0 + tx];
    __syncthreads();
    #pragma unroll
    for (int i = 0; i < 32; i += 8) {
        float v = t[tx][ty + i];                       // = w[k0+tx][n0+ty+i]
        wt[(size_t)(n0 + ty + i) * D_MOD + k0 + tx] = tf32_rna(v);
    }
}

// ---------------------------------------------------------------------------
// tf32 mma.sync GEMM: C[M,N] = A[M,K] @ Bt[N,K]^T + bias[N]
// M=4096, N=K=1024. 128x128 CTA tile, BK=16, 256 threads (8 warps, 64x32
// warp tiles). 2-stage cp.async pipeline. A and Bt MUST be pre-rounded tf32.
// ---------------------------------------------------------------------------
__global__ __launch_bounds__(256)
void gemm_tf32(const float* __restrict__ A, const float* __restrict__ Bt,
               const float* __restrict__ bias, float* __restrict__ C) {
    __shared__ float As[2][128][20];   // pitch 20 words: conflict-free frags
    __shared__ float Bs[2][128][20];

    const int tid  = threadIdx.x;
    const int lane = tid & 31;
    const int wid  = tid >> 5;
    const int wm   = wid >> 2;        // 0..1 : 64-row band
    const int wn   = wid & 3;         // 0..3 : 32-col band
    const int m0   = blockIdx.y * 128;
    const int n0   = blockIdx.x * 128;

    auto issue = [&](int kc, int st) {
        #pragma unroll
        for (int it = 0; it < 2; ++it) {
            int idx = tid + it * 256;
            int row = idx >> 2, seg = (idx & 3) * 4;
            const float* gA = A + (size_t)(m0 + row) * D_MOD + kc * 16 + seg;
            uint32_t sA = (uint32_t)__cvta_generic_to_shared(&As[st][row][seg]);
            asm volatile("cp.async.cg.shared.global [%0], [%1], 16;"
                         :: "r"(sA), "l"(gA));
            const float* gB = Bt + (size_t)(n0 + row) * D_MOD + kc * 16 + seg;
            uint32_t sB = (uint32_t)__cvta_generic_to_shared(&Bs[st][row][seg]);
            asm volatile("cp.async.cg.shared.global [%0], [%1], 16;"
                         :: "r"(sB), "l"(gB));
        }
        asm volatile("cp.async.commit_group;");
    };

    float acc[4][4][4];
    #pragma unroll
    for (int mt = 0; mt < 4; ++mt)
        #pragma unroll
        for (int nt = 0; nt < 4; ++nt)
            #pragma unroll
            for (int r = 0; r < 4; ++r) acc[mt][nt][r] = 0.f;

    issue(0, 0);

    const int NKC = D_MOD / 16;   // 64
    for (int kc = 0; kc < NKC; ++kc) {
        const int cur = kc & 1;
        if (kc + 1 < NKC) {
            issue(kc + 1, cur ^ 1);
            asm volatile("cp.async.wait_group 1;");
        } else {
            asm volatile("cp.async.wait_group 0;");
        }
        __syncthreads();

        #pragma unroll
        for (int ks = 0; ks < 2; ++ks) {
            const int g  = lane >> 2;           // groupID
            const int ac = ks * 8 + (lane & 3); // k index (frag col)
            uint32_t a[4][4], b[4][2];
            #pragma unroll
            for (int mt = 0; mt < 4; ++mt) {
                const int r = wm * 64 + mt * 16 + g;
                a[mt][0] = __float_as_uint(As[cur][r][ac]);
                a[mt][1] = __float_as_uint(As[cur][r + 8][ac]);
                a[mt][2] = __float_as_uint(As[cur][r][ac + 4]);
                a[mt][3] = __float_as_uint(As[cur][r + 8][ac + 4]);
            }
            #pragma unroll
            for (int nt = 0; nt < 4; ++nt) {
                const int n = wn * 32 + nt * 8 + g;
                b[nt][0] = __float_as_uint(Bs[cur][n][ac]);
                b[nt][1] = __float_as_uint(Bs[cur][n][ac + 4]);
            }
            #pragma unroll
            for (int mt = 0; mt < 4; ++mt)
                #pragma unroll
                for (int nt = 0; nt < 4; ++nt)
                    asm volatile(
                        "mma.sync.aligned.m16n8k8.row.col.f32.tf32.tf32.f32 "
                        "{%0,%1,%2,%3}, {%4,%5,%6,%7}, {%8,%9}, {%0,%1,%2,%3};"
                        : "+f"(acc[mt][nt][0]), "+f"(acc[mt][nt][1]),
                          "+f"(acc[mt][nt][2]), "+f"(acc[mt][nt][3])
                        : "r"(a[mt][0]), "r"(a[mt][1]),
                          "r"(a[mt][2]), "r"(a[mt][3]),
                          "r"(b[nt][0]), "r"(b[nt][1]));
        }
        __syncthreads();
    }

    // Epilogue: c0,c1 at (g, 2t..2t+1); c2,c3 at (g+8, 2t..2t+1)
    #pragma unroll
    for (int mt = 0; mt < 4; ++mt) {
        const int r0 = m0 + wm * 64 + mt * 16 + (lane >> 2);
        #pragma unroll
        for (int nt = 0; nt < 4; ++nt) {
            const int col = n0 + wn * 32 + nt * 8 + (lane & 3) * 2;
            const float2 bv = *(const float2*)&bias[col];
            float2 o0, o1;
            o0.x = acc[mt][nt][0] + bv.x;
            o0.y = acc[mt][nt][1] + bv.y;
            o1.x = acc[mt][nt][2] + bv.x;
            o1.y = acc[mt][nt][3] + bv.y;
            *(float2*)&C[(size_t)r0 * NCOL + col] = o0;
            *(float2*)&C[(size_t)(r0 + 8) * NCOL + col] = o1;
        }
    }
}

// ---------------------------------------------------------------------------
// Causal flash attention, fp32 (round-3 kernel; output rounded to tf32 so
// the following GEMM needs no operand conversion).
// ---------------------------------------------------------------------------
#define BQ 64
#define SPITCH 65

__global__ __launch_bounds__(256)
void flash_attn(const float* __restrict__ q, const float* __restrict__ k,
                const float* __restrict__ v, float* __restrict__ o) {
    const int qt = blockIdx.x;
    const int h  = blockIdx.y;
    const int b  = blockIdx.z;

    extern __shared__ float sm[];
    float* Qs   = sm;
    float* Ks   = Qs + 64 * SPITCH;
    float* Vs   = Ks + 64 * SPITCH;
    float* S    = Vs + 64 * SPITCH;
    float* rowc = S + 64 * SPITCH;
    float* rowl = rowc + 64;

    const int tid = threadIdx.x;
    const int tx = tid & 15;
    const int ty = tid >> 4;
    const int tx4 = tx * 4;
    const int ty4 = ty * 4;
    const int q0 = qt * BQ;
    const float scale = 0.125f;

    #pragma unroll
    for (int it = 0; it < 4; ++it) {
        int row = (tid >> 4) + it * 16;
        int c4  = (tid & 15) * 4;
        float4 vq = *(const float4*)&q[(size_t)(b * T_SEQ + q0 + row) * NCOL + h * DH + c4];
        float* dst = &Qs[row * SPITCH + c4];
        dst[0] = vq.x; dst[1] = vq.y; dst[2] = vq.z; dst[3] = vq.w;
    }

    float m_reg = -1e30f, l_reg = 0.f;
    float oacc[4][4];
    #pragma unroll
    for (int i = 0; i < 4; ++i)
        #pragma unroll
        for (int j = 0; j < 4; ++j) oacc[i][j] = 0.f;

    for (int kt = 0; kt <= qt; ++kt) {
        const int k0 = kt * BQ;
        __syncthreads();

        #pragma unroll
        for (int it = 0; it < 4; ++it) {
            int row = (tid >> 4) + it * 16;
            int c4  = (tid & 15) * 4;
            size_t base = (size_t)(b * T_SEQ + k0 + row) * NCOL + h * DH + c4;
            float4 vk = *(const float4*)&k[base];
            float4 vv = *(const float4*)&v[base];
            float* dk = &Ks[row * SPITCH + c4];
            dk[0] = vk.x; dk[1] = vk.y; dk[2] = vk.z; dk[3] = vk.w;
            float* dv = &Vs[row * SPITCH + c4];
            dv[0] = vv.x; dv[1] = vv.y; dv[2] = vv.z; dv[3] = vv.w;
        }
        __syncthreads();

        float sacc[4][4];
        #pragma unroll
        for (int i = 0; i < 4; ++i)
            #pragma unroll
            for (int j = 0; j < 4; ++j) sacc[i][j] = 0.f;

        #pragma unroll 16
        for (int d = 0; d < DH; ++d) {
            float qf[4], kf[4];
            #pragma unroll
            for (int i = 0; i < 4; ++i) qf[i] = Qs[(ty4 + i) * SPITCH + d];
            #pragma unroll
            for (int j = 0; j < 4; ++j) kf[j] = Ks[(tx4 + j) * SPITCH + d];
            #pragma unroll
            for (int i = 0; i < 4; ++i)
                #pragma unroll
                for (int j = 0; j < 4; ++j)
                    sacc[i][j] += qf[i] * kf[j];
        }

        const bool diag = (kt == qt);
        #pragma unroll
        for (int i = 0; i < 4; ++i)
            #pragma unroll
            for (int j = 0; j < 4; ++j) {
                float s = sacc[i][j] * scale;
                if (diag && (k0 + tx4 + j) > (q0 + ty4 + i)) s = -1e30f;
                S[(ty4 + i) * SPITCH + tx4 + j] = s;
            }
        __syncthreads();

        if (tid < 64) {
            const float* srow = &S[tid * SPITCH];
            float m_new = m_reg;
            #pragma unroll 8
            for (int j = 0; j < BQ; ++j) m_new = fmaxf(m_new, srow[j]);
            float c = __expf(m_reg - m_new);
            float lsum = 0.f;
            float* prow = &S[tid * SPITCH];
            #pragma unroll 8
            for (int j = 0; j < BQ; ++j) {
                float p = __expf(srow[j] - m_new);
                prow[j] = p;
                lsum += p;
            }
            l_reg = l_reg * c + lsum;
            m_reg = m_new;
            rowc[tid] = c;
        }
        __syncthreads();

        float ci[4];
        #pragma unroll
        for (int i = 0; i < 4; ++i) ci[i] = rowc[ty4 + i];
        #pragma unroll
        for (int i = 0; i < 4; ++i)
            #pragma unroll
            for (int j = 0; j < 4; ++j) oacc[i][j] *= ci[i];

        #pragma unroll 8
        for (int jj = 0; jj < BQ; ++jj) {
            float pv[4], vv[4];
            #pragma unroll
            for (int i = 0; i < 4; ++i) pv[i] = S[(ty4 + i) * SPITCH + jj];
            #pragma unroll
            for (int j = 0; j < 4; ++j) vv[j] = Vs[jj * SPITCH + tx4 + j];
            #pragma unroll
            for (int i = 0; i < 4; ++i)
                #pragma unroll
                for (int j = 0; j < 4; ++j)
                    oacc[i][j] += pv[i] * vv[j];
        }
    }

    if (tid < 64) rowl[tid] = 1.0f / l_reg;
    __syncthreads();

    float inv[4];
    #pragma unroll
    for (int i = 0; i < 4; ++i) inv[i] = rowl[ty4 + i];
    #pragma unroll
    for (int i = 0; i < 4; ++i) {
        size_t base = (size_t)(b * T_SEQ + q0 + ty4 + i) * NCOL + h * DH + tx4;
        float4 vo;
        vo.x = tf32_rna(oacc[i][0] * inv[i]);   // pre-round for the wo GEMM
        vo.y = tf32_rna(oacc[i][1] * inv[i]);
        vo.z = tf32_rna(oacc[i][2] * inv[i]);
        vo.w = tf32_rna(oacc[i][3] * inv[i]);
        *(float4*)&o[base] = vo;
    }
}

// ---------------------------------------------------------------------------
// Launch
// ---------------------------------------------------------------------------
extern "C" void kernel_launch(void* const* d_in, const int* in_sizes, int n_in,
                              void* d_out, int out_size) {
    const float* x  = (const float*)d_in[0];
    const float* wq = (const float*)d_in[1];
    const float* bq = (const float*)d_in[2];
    const float* wk = (const float*)d_in[3];
    const float* bk = (const float*)d_in[4];
    const float* wv = (const float*)d_in[5];
    const float* bv = (const float*)d_in[6];
    const float* wo = (const float*)d_in[7];
    const float* bo = (const float*)d_in[8];
    float* out = (float*)d_out;

    unsigned char* sp;
    cudaGetSymbolAddress((void**)&sp, g_scratch);
    const size_t MB = 1024u * 1024u;
    float* qp  = (float*)(sp + 0 * MB);
    float* kp  = (float*)(sp + 16 * MB);
    float* vp  = (float*)(sp + 32 * MB);
    float* ap  = (float*)(sp + 48 * MB);
    float* xr  = (float*)(sp + 64 * MB);
    float* wqT = (float*)(sp + 80 * MB);
    float* wkT = (float*)(sp + 84 * MB);
    float* wvT = (float*)(sp + 88 * MB);
    float* woT = (float*)(sp + 92 * MB);

    const int fa_smem = (4 * 64 * SPITCH + 2 * 64) * (int)sizeof(float);
    cudaFuncSetAttribute(flash_attn, cudaFuncAttributeMaxDynamicSharedMemorySize,
                         fa_smem);

    // 1) Round x to tf32 precision
    const int n4 = M_TOT * D_MOD / 4;
    round_tf32_4<<<(n4 + 255) / 256, 256>>>(x, xr, n4);

    // 2) Transpose + round the 4 weights -> [N][K]
    dim3 tg(NCOL / 32, D_MOD / 32), tb(32, 8);
    cvt_T<<<tg, tb>>>(wq, wqT);
    cvt_T<<<tg, tb>>>(wk, wkT);
    cvt_T<<<tg, tb>>>(wv, wvT);
    cvt_T<<<tg, tb>>>(wo, woT);

    // 3) QKV projections on tensor cores (tf32 mma.sync)
    dim3 gg(NCOL / 128, M_TOT / 128);
    gemm_tf32<<<gg, 256>>>(xr, wqT, bq, qp);
    gemm_tf32<<<gg, 256>>>(xr, wkT, bk, kp);
    gemm_tf32<<<gg, 256>>>(xr, wvT, bv, vp);

    // 4) Attention (fp32 SIMT; output tf32-rounded in its epilogue)
    flash_attn<<<dim3(T_SEQ / BQ, NH, B_SZ), 256, fa_smem>>>(qp, kp, vp, ap);

    // 5) Output projection on tensor cores
    gemm_tf32<<<gg, 256>>>(ap, woT, bo, out);
}

// round 8
// speedup vs baseline: 3.2363x; 2.2665x over previous
#include <cuda_runtime.h>
#include <cuda_bf16.h>
#include <cstdint>
#include <cstddef>

// Problem constants
#define B_SZ   2
#define T_SEQ  2048
#define D_MOD  1024
#define NH     16
#define DH     64
#define M_TOT  (B_SZ * T_SEQ)   // 4096 rows
#define NCOL   (NH * DH)        // 1024 cols (== D_MOD)

// ---------------------------------------------------------------------------
// Scratch carve (bytes):
//   q: 0  k: 16MB  v: 32MB  attn: 48MB  xr: 64MB  wT's: 80..96MB
#define SCRATCH_BYTES (96u * 1024u * 1024u)
__device__ __align__(256) unsigned char g_scratch[SCRATCH_BYTES];

// ---------------------------------------------------------------------------
__device__ __forceinline__ float tf32_rna(float v) {
    uint32_t u;
    asm("cvt.rna.tf32.f32 %0, %1;" : "=r"(u) : "f"(v));
    return __uint_as_float(u);
}

#define MMA_TF32(D, A, B)                                                   \
    asm volatile(                                                           \
        "mma.sync.aligned.m16n8k8.row.col.f32.tf32.tf32.f32 "               \
        "{%0,%1,%2,%3}, {%4,%5,%6,%7}, {%8,%9}, {%0,%1,%2,%3};"             \
        : "+f"((D)[0]), "+f"((D)[1]), "+f"((D)[2]), "+f"((D)[3])            \
        : "r"((A)[0]), "r"((A)[1]), "r"((A)[2]), "r"((A)[3]),               \
          "r"((B)[0]), "r"((B)[1]))

// ---------------------------------------------------------------------------
// Elementwise tf32 rounding (x -> xr), vectorized x4
// ---------------------------------------------------------------------------
__global__ __launch_bounds__(256)
void round_tf32_4(const float* __restrict__ in, float* __restrict__ out, int n4) {
    int i = blockIdx.x * blockDim.x + threadIdx.x;
    if (i >= n4) return;
    float4 v = ((const float4*)in)[i];
    v.x = tf32_rna(v.x);
    v.y = tf32_rna(v.y);
    v.z = tf32_rna(v.z);
    v.w = tf32_rna(v.w);
    ((float4*)out)[i] = v;
}

// ---------------------------------------------------------------------------
// Weight transpose + tf32 round: w[K][N] -> wT[N][K]
// ---------------------------------------------------------------------------
__global__ __launch_bounds__(256)
void cvt_T(const float* __restrict__ w, float* __restrict__ wt) {
    __shared__ float t[32][33];
    const int n0 = blockIdx.x * 32;
    const int k0 = blockIdx.y * 32;
    const int tx = threadIdx.x;
    const int ty = threadIdx.y;
    #pragma unroll
    for (int i = 0; i < 32; i += 8)
        t[ty + i][tx] = w[(size_t)(k0 + ty + i) * NCOL + n0 + tx];
    __syncthreads();
    #pragma unroll
    for (int i = 0; i < 32; i += 8) {
        float v = t[tx][ty + i];
        wt[(size_t)(n0 + ty + i) * D_MOD + k0 + tx] = tf32_rna(v);
    }
}

// ---------------------------------------------------------------------------
// tf32 mma.sync GEMM (unchanged from round 6): C = A @ Bt^T + bias
// ---------------------------------------------------------------------------
__global__ __launch_bounds__(256)
void gemm_tf32(const float* __restrict__ A, const float* __restrict__ Bt,
               const float* __restrict__ bias, float* __restrict__ C) {
    __shared__ float As[2][128][20];
    __shared__ float Bs[2][128][20];

    const int tid  = threadIdx.x;
    const int lane = tid & 31;
    const int wid  = tid >> 5;
    const int wm   = wid >> 2;
    const int wn   = wid & 3;
    const int m0   = blockIdx.y * 128;
    const int n0   = blockIdx.x * 128;

    auto issue = [&](int kc, int st) {
        #pragma unroll
        for (int it = 0; it < 2; ++it) {
            int idx = tid + it * 256;
            int row = idx >> 2, seg = (idx & 3) * 4;
            const float* gA = A + (size_t)(m0 + row) * D_MOD + kc * 16 + seg;
            uint32_t sA = (uint32_t)__cvta_generic_to_shared(&As[st][row][seg]);
            asm volatile("cp.async.cg.shared.global [%0], [%1], 16;"
                         :: "r"(sA), "l"(gA));
            const float* gB = Bt + (size_t)(n0 + row) * D_MOD + kc * 16 + seg;
            uint32_t sB = (uint32_t)__cvta_generic_to_shared(&Bs[st][row][seg]);
            asm volatile("cp.async.cg.shared.global [%0], [%1], 16;"
                         :: "r"(sB), "l"(gB));
        }
        asm volatile("cp.async.commit_group;");
    };

    float acc[4][4][4];
    #pragma unroll
    for (int mt = 0; mt < 4; ++mt)
        #pragma unroll
        for (int nt = 0; nt < 4; ++nt)
            #pragma unroll
            for (int r = 0; r < 4; ++r) acc[mt][nt][r] = 0.f;

    issue(0, 0);

    const int NKC = D_MOD / 16;
    for (int kc = 0; kc < NKC; ++kc) {
        const int cur = kc & 1;
        if (kc + 1 < NKC) {
            issue(kc + 1, cur ^ 1);
            asm volatile("cp.async.wait_group 1;");
        } else {
            asm volatile("cp.async.wait_group 0;");
        }
        __syncthreads();

        #pragma unroll
        for (int ks = 0; ks < 2; ++ks) {
            const int g  = lane >> 2;
            const int ac = ks * 8 + (lane & 3);
            uint32_t a[4][4], b[4][2];
            #pragma unroll
            for (int mt = 0; mt < 4; ++mt) {
                const int r = wm * 64 + mt * 16 + g;
                a[mt][0] = __float_as_uint(As[cur][r][ac]);
                a[mt][1] = __float_as_uint(As[cur][r + 8][ac]);
                a[mt][2] = __float_as_uint(As[cur][r][ac + 4]);
                a[mt][3] = __float_as_uint(As[cur][r + 8][ac + 4]);
            }
            #pragma unroll
            for (int nt = 0; nt < 4; ++nt) {
                const int n = wn * 32 + nt * 8 + g;
                b[nt][0] = __float_as_uint(Bs[cur][n][ac]);
                b[nt][1] = __float_as_uint(Bs[cur][n][ac + 4]);
            }
            #pragma unroll
            for (int mt = 0; mt < 4; ++mt)
                #pragma unroll
                for (int nt = 0; nt < 4; ++nt)
                    MMA_TF32(acc[mt][nt], a[mt], b[nt]);
        }
        __syncthreads();
    }

    #pragma unroll
    for (int mt = 0; mt < 4; ++mt) {
        const int r0 = m0 + wm * 64 + mt * 16 + (lane >> 2);
        #pragma unroll
        for (int nt = 0; nt < 4; ++nt) {
            const int col = n0 + wn * 32 + nt * 8 + (lane & 3) * 2;
            const float2 bv = *(const float2*)&bias[col];
            float2 o0, o1;
            o0.x = acc[mt][nt][0] + bv.x;
            o0.y = acc[mt][nt][1] + bv.y;
            o1.x = acc[mt][nt][2] + bv.x;
            o1.y = acc[mt][nt][3] + bv.y;
            *(float2*)&C[(size_t)r0 * NCOL + col] = o0;
            *(float2*)&C[(size_t)(r0 + 8) * NCOL + col] = o1;
        }
    }
}

// ---------------------------------------------------------------------------
// Causal flash attention on tf32 mma.sync.
// CTA = 128 threads (4 warps); each warp owns 16 q-rows of a 64-row tile.
// Grid: (32 qtiles, 16 heads, 2 batch). Q frags hoisted; Qs smem aliased as Ps.
// ---------------------------------------------------------------------------
#define QP 68   // pitch: (row g)*QP + t conflict-free (4g+t distinct mod 32)
#define VP 72   // pitch: (row t)*VP + g conflict-free (8t+g distinct mod 32)
#define FA_SMEM ((64 * QP + 64 * QP + 64 * VP) * 4)

__global__ __launch_bounds__(128)
void flash_attn_mma(const float* __restrict__ q, const float* __restrict__ k,
                    const float* __restrict__ v, float* __restrict__ o) {
    const int qt = (int)gridDim.x - 1 - blockIdx.x;  // long CTAs first
    const int h  = blockIdx.y;
    const int b  = blockIdx.z;

    extern __shared__ float sm[];
    float* Qs = sm;              // 64 x QP   (reused as Ps after frag hoist)
    float* Ks = sm + 64 * QP;    // 64 x QP
    float* Vs = Ks + 64 * QP;    // 64 x VP
    float* Ps = Qs;

    const int tid  = threadIdx.x;
    const int lane = tid & 31;
    const int w    = tid >> 5;
    const int g    = lane >> 2;
    const int t    = lane & 3;
    const int w16  = w * 16;
    const int q0   = qt * 64;

    // Load Q tile, fold in softmax scale (2^-3: exact), round to tf32.
    #pragma unroll
    for (int it = 0; it < 8; ++it) {
        int idx = tid + it * 128;
        int row = idx >> 4, c4 = (idx & 15) * 4;
        float4 vq = *(const float4*)&q[(size_t)(b * T_SEQ + q0 + row) * NCOL + h * DH + c4];
        float* d = &Qs[row * QP + c4];
        d[0] = tf32_rna(vq.x * 0.125f);
        d[1] = tf32_rna(vq.y * 0.125f);
        d[2] = tf32_rna(vq.z * 0.125f);
        d[3] = tf32_rna(vq.w * 0.125f);
    }
    __syncthreads();

    // Hoist Q A-fragments (loop-invariant)
    uint32_t qa[8][4];
    #pragma unroll
    for (int ks = 0; ks < 8; ++ks) {
        const int c = ks * 8 + t;
        qa[ks][0] = __float_as_uint(Qs[(w16 + g) * QP + c]);
        qa[ks][1] = __float_as_uint(Qs[(w16 + g + 8) * QP + c]);
        qa[ks][2] = __float_as_uint(Qs[(w16 + g) * QP + c + 4]);
        qa[ks][3] = __float_as_uint(Qs[(w16 + g + 8) * QP + c + 4]);
    }

    float mA = -1e30f, mB = -1e30f, lA = 0.f, lB = 0.f;
    float oacc[8][4];
    #pragma unroll
    for (int nt = 0; nt < 8; ++nt)
        #pragma unroll
        for (int r = 0; r < 4; ++r) oacc[nt][r] = 0.f;

    for (int kt = 0; kt <= qt; ++kt) {
        __syncthreads();   // Ks/Vs free; also protects Ps(=Qs) reuse on iter 0

        // Load K/V tiles (tf32-rounded)
        #pragma unroll
        for (int it = 0; it < 8; ++it) {
            int idx = tid + it * 128;
            int row = idx >> 4, c4 = (idx & 15) * 4;
            size_t base = (size_t)(b * T_SEQ + kt * 64 + row) * NCOL + h * DH + c4;
            float4 kk = *(const float4*)&k[base];
            float4 vv = *(const float4*)&v[base];
            float* dk = &Ks[row * QP + c4];
            dk[0] = tf32_rna(kk.x); dk[1] = tf32_rna(kk.y);
            dk[2] = tf32_rna(kk.z); dk[3] = tf32_rna(kk.w);
            float* dv = &Vs[row * VP + c4];
            dv[0] = tf32_rna(vv.x); dv[1] = tf32_rna(vv.y);
            dv[2] = tf32_rna(vv.z); dv[3] = tf32_rna(vv.w);
        }
        __syncthreads();

        // S = Q K^T via HMMA
        float sacc[8][4];
        #pragma unroll
        for (int nt = 0; nt < 8; ++nt)
            #pragma unroll
            for (int r = 0; r < 4; ++r) sacc[nt][r] = 0.f;

        #pragma unroll
        for (int ks = 0; ks < 8; ++ks) {
            const int c = ks * 8 + t;
            #pragma unroll
            for (int nt = 0; nt < 8; ++nt) {
                uint32_t bb[2];
                bb[0] = __float_as_uint(Ks[(nt * 8 + g) * QP + c]);
                bb[1] = __float_as_uint(Ks[(nt * 8 + g) * QP + c + 4]);
                MMA_TF32(sacc[nt], qa[ks], bb);
            }
        }

        // Causal mask (diag tile only; earlier tiles fully unmasked)
        if (kt == qt) {
            const int rA = w16 + g, rB = rA + 8;
            #pragma unroll
            for (int nt = 0; nt < 8; ++nt) {
                const int c0 = nt * 8 + 2 * t, c1 = c0 + 1;
                if (c0 > rA) sacc[nt][0] = -1e30f;
                if (c1 > rA) sacc[nt][1] = -1e30f;
                if (c0 > rB) sacc[nt][2] = -1e30f;
                if (c1 > rB) sacc[nt][3] = -1e30f;
            }
        }

        // Row max (registers + quad shuffle)
        float rmA = -1e30f, rmB = -1e30f;
        #pragma unroll
        for (int nt = 0; nt < 8; ++nt) {
            rmA = fmaxf(rmA, fmaxf(sacc[nt][0], sacc[nt][1]));
            rmB = fmaxf(rmB, fmaxf(sacc[nt][2], sacc[nt][3]));
        }
        rmA = fmaxf(rmA, __shfl_xor_sync(0xffffffffu, rmA, 1));
        rmA = fmaxf(rmA, __shfl_xor_sync(0xffffffffu, rmA, 2));
        rmB = fmaxf(rmB, __shfl_xor_sync(0xffffffffu, rmB, 1));
        rmB = fmaxf(rmB, __shfl_xor_sync(0xffffffffu, rmB, 2));

        const float mnA = fmaxf(mA, rmA);
        const float mnB = fmaxf(mB, rmB);
        const float cA = __expf(mA - mnA);
        const float cB = __expf(mB - mnB);

        // Exponentiate fragments, accumulate row sums
        float sA = 0.f, sB = 0.f;
        #pragma unroll
        for (int nt = 0; nt < 8; ++nt) {
            sacc[nt][0] = __expf(sacc[nt][0] - mnA);
            sacc[nt][1] = __expf(sacc[nt][1] - mnA);
            sacc[nt][2] = __expf(sacc[nt][2] - mnB);
            sacc[nt][3] = __expf(sacc[nt][3] - mnB);
            sA += sacc[nt][0] + sacc[nt][1];
            sB += sacc[nt][2] + sacc[nt][3];
        }
        sA += __shfl_xor_sync(0xffffffffu, sA, 1);
        sA += __shfl_xor_sync(0xffffffffu, sA, 2);
        sB += __shfl_xor_sync(0xffffffffu, sB, 1);
        sB += __shfl_xor_sync(0xffffffffu, sB, 2);
        lA = lA * cA + sA;
        lB = lB * cB + sB;
        mA = mnA;
        mB = mnB;

        // Rescale O accumulators
        #pragma unroll
        for (int nt = 0; nt < 8; ++nt) {
            oacc[nt][0] *= cA; oacc[nt][1] *= cA;
            oacc[nt][2] *= cB; oacc[nt][3] *= cB;
        }

        // Store P (tf32) to warp-private smem region
        #pragma unroll
        for (int nt = 0; nt < 8; ++nt) {
            const int c0 = nt * 8 + 2 * t;
            float2 p0, p1;
            p0.x = tf32_rna(sacc[nt][0]); p0.y = tf32_rna(sacc[nt][1]);
            p1.x = tf32_rna(sacc[nt][2]); p1.y = tf32_rna(sacc[nt][3]);
            *(float2*)&Ps[(w16 + g) * QP + c0]     = p0;
            *(float2*)&Ps[(w16 + g + 8) * QP + c0] = p1;
        }
        __syncwarp();

        // O += P @ V via HMMA
        #pragma unroll
        for (int ks = 0; ks < 8; ++ks) {
            const int c = ks * 8 + t;
            uint32_t pa[4];
            pa[0] = __float_as_uint(Ps[(w16 + g) * QP + c]);
            pa[1] = __float_as_uint(Ps[(w16 + g + 8) * QP + c]);
            pa[2] = __float_as_uint(Ps[(w16 + g) * QP + c + 4]);
            pa[3] = __float_as_uint(Ps[(w16 + g + 8) * QP + c + 4]);
            #pragma unroll
            for (int nt = 0; nt < 8; ++nt) {
                uint32_t bb[2];
                bb[0] = __float_as_uint(Vs[(ks * 8 + t) * VP + nt * 8 + g]);
                bb[1] = __float_as_uint(Vs[(ks * 8 + t + 4) * VP + nt * 8 + g]);
                MMA_TF32(oacc[nt], pa, bb);
            }
        }
        __syncwarp();   // PV reads done before next iter's Ps writes
    }

    // Epilogue: normalize, tf32-round (input to wo GEMM), store
    const float invA = 1.0f / lA;
    const float invB = 1.0f / lB;
    const int rA = b * T_SEQ + q0 + w16 + g;
    const int rB = rA + 8;
    #pragma unroll
    for (int nt = 0; nt < 8; ++nt) {
        const int col = h * DH + nt * 8 + 2 * t;
        float2 o0, o1;
        o0.x = tf32_rna(oacc[nt][0] * invA);
        o0.y = tf32_rna(oacc[nt][1] * invA);
        o1.x = tf32_rna(oacc[nt][2] * invB);
        o1.y = tf32_rna(oacc[nt][3] * invB);
        *(float2*)&o[(size_t)rA * NCOL + col] = o0;
        *(float2*)&o[(size_t)rB * NCOL + col] = o1;
    }
}

// ---------------------------------------------------------------------------
// Launch
// ---------------------------------------------------------------------------
extern "C" void kernel_launch(void* const* d_in, const int* in_sizes, int n_in,
                              void* d_out, int out_size) {
    const float* x  = (const float*)d_in[0];
    const float* wq = (const float*)d_in[1];
    const float* bq = (const float*)d_in[2];
    const float* wk = (const float*)d_in[3];
    const float* bk = (const float*)d_in[4];
    const float* wv = (const float*)d_in[5];
    const float* bv = (const float*)d_in[6];
    const float* wo = (const float*)d_in[7];
    const float* bo = (const float*)d_in[8];
    float* out = (float*)d_out;

    unsigned char* sp;
    cudaGetSymbolAddress((void**)&sp, g_scratch);
    const size_t MB = 1024u * 1024u;
    float* qp  = (float*)(sp + 0 * MB);
    float* kp  = (float*)(sp + 16 * MB);
    float* vp  = (float*)(sp + 32 * MB);
    float* ap  = (float*)(sp + 48 * MB);
    float* xr  = (float*)(sp + 64 * MB);
    float* wqT = (float*)(sp + 80 * MB);
    float* wkT = (float*)(sp + 84 * MB);
    float* wvT = (float*)(sp + 88 * MB);
    float* woT = (float*)(sp + 92 * MB);

    cudaFuncSetAttribute(flash_attn_mma,
                         cudaFuncAttributeMaxDynamicSharedMemorySize, FA_SMEM);

    // 1) Round x to tf32 precision
    const int n4 = M_TOT * D_MOD / 4;
    round_tf32_4<<<(n4 + 255) / 256, 256>>>(x, xr, n4);

    // 2) Transpose + round the 4 weights -> [N][K]
    dim3 tg(NCOL / 32, D_MOD / 32), tb(32, 8);
    cvt_T<<<tg, tb>>>(wq, wqT);
    cvt_T<<<tg, tb>>>(wk, wkT);
    cvt_T<<<tg, tb>>>(wv, wvT);
    cvt_T<<<tg, tb>>>(wo, woT);

    // 3) QKV projections (tf32 mma.sync)
    dim3 gg(NCOL / 128, M_TOT / 128);
    gemm_tf32<<<gg, 256>>>(xr, wqT, bq, qp);
    gemm_tf32<<<gg, 256>>>(xr, wkT, bk, kp);
    gemm_tf32<<<gg, 256>>>(xr, wvT, bv, vp);

    // 4) Attention on tensor cores
    flash_attn_mma<<<dim3(T_SEQ / 64, NH, B_SZ), 128, FA_SMEM>>>(qp, kp, vp, ap);

    // 5) Output projection (tf32 mma.sync)
    gemm_tf32<<<gg, 256>>>(ap, woT, bo, out);
}